// round 16
// baseline (speedup 1.0000x reference)
#include <cuda_runtime.h>
#include <cstdint>

#define NN 100000
#define NE 1600000
#define DIN 128
#define DHID 128
#define NCLS 64

// ---------------- device scratch — symbols only, NEVER passed from host ------
__device__ __align__(16) float r16_h[(size_t)NN * 128];
__device__ __align__(16) float r16_a[(size_t)NN * 128];
__device__ __align__(16) float r16_dinv[NN];
__device__ __align__(16) int   r16_cnt[NN];
__device__ __align__(16) int   r16_rs[NN];
__device__ __align__(16) int   r16_wcur[NN];
__device__ __align__(16) int   r16_col[NE];
__device__ __align__(16) int   r16_bsum[256];

// ---------------- graph build (int32 planar [2,E]) ---------------------------
__global__ void r16_zcnt(int n) {
    int i = blockIdx.x * blockDim.x + threadIdx.x;
    if (i < n) r16_cnt[i] = 0;
}
__global__ void r16_hist(const int* __restrict__ ep, int e, int n) {
    int i = blockIdx.x * blockDim.x + threadIdx.x;
    if (i < e) {
        int d = ep[e + i];
        if (d >= 0 && d < n) atomicAdd(&r16_cnt[d], 1);
    }
}
__global__ void r16_dinvk(int n) {
    int i = blockIdx.x * blockDim.x + threadIdx.x;
    if (i < n) r16_dinv[i] = rsqrtf((float)(r16_cnt[i] + 1));   // +1 self loop
}
__global__ void r16_scan1(int n) {
    __shared__ int s[1024];
    int lid = threadIdx.x, gid = blockIdx.x * 1024 + lid;
    int v = (gid < n) ? r16_cnt[gid] : 0;
    s[lid] = v; __syncthreads();
    for (int off = 1; off < 1024; off <<= 1) {
        int t = (lid >= off) ? s[lid - off] : 0;
        __syncthreads(); s[lid] += t; __syncthreads();
    }
    if (gid < n) r16_rs[gid] = s[lid] - v;
    if (lid == 1023) r16_bsum[blockIdx.x] = s[1023];
}
__global__ void r16_scan2(int nb) {
    __shared__ int s[256];
    int lid = threadIdx.x;
    int v = (lid < nb) ? r16_bsum[lid] : 0;
    s[lid] = v; __syncthreads();
    for (int off = 1; off < 256; off <<= 1) {
        int t = (lid >= off) ? s[lid - off] : 0;
        __syncthreads(); s[lid] += t; __syncthreads();
    }
    if (lid < nb) r16_bsum[lid] = s[lid] - v;
}
__global__ void r16_scan3(int n) {
    int gid = blockIdx.x * 1024 + threadIdx.x;
    if (gid < n) {
        int r = r16_rs[gid] + r16_bsum[blockIdx.x];
        r16_rs[gid] = r; r16_wcur[gid] = r;
    }
}
__global__ void r16_fill(const int* __restrict__ ep, int e, int n) {
    int i = blockIdx.x * blockDim.x + threadIdx.x;
    if (i < e) {
        int s = ep[i], d = ep[e + i];
        if (d >= 0 && d < n && s >= 0 && s < n) {
            int pos = atomicAdd(&r16_wcur[d], 1);
            if (pos >= 0 && pos < NE) r16_col[pos] = s;
        }
    }
}

// ---------------- GEMM with packed fma.rn.f32x2 ------------------------------
// out[row,:] = dinv[row] * (X[row,:] @ W).  SRC=0: X=param; SRC=1: X=r16_a.
// Row-pairs packed into b64 accumulators; W duplicated in smem so both FFMA2
// operands load directly as u64 (no per-k repacking).
template <int BN, int NCH, int SRC>
__global__ void __launch_bounds__(256) r16_gemm(
    const float* __restrict__ Xparam, const float* __restrict__ W, int nrows)
{
    constexpr int BM = 128, BK = 16;
    __shared__ __align__(16) float Xs[BK][BM + 2];     // stride 130: rows 8B-aligned
    __shared__ __align__(16) float Ws2[BK][2 * BN];    // each W value duplicated
    const float* X = (SRC == 0) ? Xparam : r16_a;
    float* out = r16_h;

    int t = threadIdx.x, rg = t >> 4, cg = t & 15;
    int blockRow = blockIdx.x * BM;

    unsigned long long acc2[4][4 * NCH];               // [row-pair][col]
#pragma unroll
    for (int p = 0; p < 4; p++)
#pragma unroll
        for (int j = 0; j < 4 * NCH; j++) acc2[p][j] = 0ULL;

    for (int kb = 0; kb < 128; kb += BK) {
        // X tile (128 rows x 16 k), transposed into Xs[k][row]
#pragma unroll
        for (int it = 0; it < 2; it++) {
            int f = t + it * 256, row = f >> 2, kq = (f & 3) * 4;
            float4 v = make_float4(0.f, 0.f, 0.f, 0.f);
            int gr = blockRow + row;
            if (gr < nrows)
                v = *reinterpret_cast<const float4*>(X + (size_t)gr * 128 + kb + kq);
            Xs[kq + 0][row] = v.x; Xs[kq + 1][row] = v.y;
            Xs[kq + 2][row] = v.z; Xs[kq + 3][row] = v.w;
        }
        // W tile, duplicated: Ws2[k][2c] = Ws2[k][2c+1] = W[k][c]
#pragma unroll
        for (int it = 0; it < (BK * BN) / 256; it++) {
            int f = t + it * 256;
            int kr = f / BN, nc = f % BN;
            float w = W[(size_t)(kb + kr) * BN + nc];
            unsigned long long ww;
            asm("mov.b64 %0, {%1, %1};" : "=l"(ww) : "f"(w));
            *reinterpret_cast<unsigned long long*>(&Ws2[kr][2 * nc]) = ww;
        }
        __syncthreads();

#pragma unroll
        for (int k = 0; k < BK; k++) {
            unsigned long long av2[4];                 // row pairs
            av2[0] = *reinterpret_cast<const unsigned long long*>(&Xs[k][rg * 4]);
            av2[1] = *reinterpret_cast<const unsigned long long*>(&Xs[k][rg * 4 + 2]);
            av2[2] = *reinterpret_cast<const unsigned long long*>(&Xs[k][64 + rg * 4]);
            av2[3] = *reinterpret_cast<const unsigned long long*>(&Xs[k][64 + rg * 4 + 2]);
            unsigned long long bv2[4 * NCH];           // duplicated W values
#pragma unroll
            for (int h = 0; h < NCH; h++) {
                const unsigned long long* wp = reinterpret_cast<const unsigned long long*>(
                    &Ws2[k][2 * (h * 64 + cg * 4)]);
                bv2[h * 4 + 0] = wp[0]; bv2[h * 4 + 1] = wp[1];
                bv2[h * 4 + 2] = wp[2]; bv2[h * 4 + 3] = wp[3];
            }
#pragma unroll
            for (int p = 0; p < 4; p++)
#pragma unroll
                for (int j = 0; j < 4 * NCH; j++)
                    asm("fma.rn.f32x2 %0, %1, %2, %0;"
                        : "+l"(acc2[p][j]) : "l"(av2[p]), "l"(bv2[j]));
        }
        __syncthreads();
    }

    // epilogue: unpack pairs, scale by dinv, vector store
#pragma unroll
    for (int p = 0; p < 4; p++) {
        int rowlo = blockRow + ((p < 2) ? (rg * 4 + 2 * p) : (64 + rg * 4 + 2 * (p - 2)));
#pragma unroll
        for (int half = 0; half < 2; half++) {
            int row = rowlo + half;
            if (row < nrows) {
                float di = r16_dinv[row];
#pragma unroll
                for (int h = 0; h < NCH; h++) {
                    float4 v;
                    unsigned long long a0 = acc2[p][h * 4 + 0], a1 = acc2[p][h * 4 + 1];
                    unsigned long long a2 = acc2[p][h * 4 + 2], a3 = acc2[p][h * 4 + 3];
                    v.x = __uint_as_float(half ? (unsigned)(a0 >> 32) : (unsigned)a0) * di;
                    v.y = __uint_as_float(half ? (unsigned)(a1 >> 32) : (unsigned)a1) * di;
                    v.z = __uint_as_float(half ? (unsigned)(a2 >> 32) : (unsigned)a2) * di;
                    v.w = __uint_as_float(half ? (unsigned)(a3 >> 32) : (unsigned)a3) * di;
                    *reinterpret_cast<float4*>(out + (size_t)row * BN + h * 64 + cg * 4) = v;
                }
            }
        }
    }
}

// ---------------- aggregations (MLP-4 gather unroll) --------------------------
__global__ void __launch_bounds__(256) r16_agg1(const float* __restrict__ b1, int n) {
    int warp = (blockIdx.x * blockDim.x + threadIdx.x) >> 5;
    int lane = threadIdx.x & 31;
    if (warp >= n) return;
    int i = warp, c0 = lane * 4;
    float4 acc = *reinterpret_cast<const float4*>(r16_h + (size_t)i * 128 + c0);
    int start = r16_rs[i], deg = r16_cnt[i];
    for (int j = 0; j < deg; j += 32) {
        int c = (j + lane < deg) ? r16_col[start + j + lane] : 0;
        int m = min(32, deg - j);
        int jj = 0;
        for (; jj + 4 <= m; jj += 4) {
            int s0 = __shfl_sync(0xffffffffu, c, jj);
            int s1 = __shfl_sync(0xffffffffu, c, jj + 1);
            int s2 = __shfl_sync(0xffffffffu, c, jj + 2);
            int s3 = __shfl_sync(0xffffffffu, c, jj + 3);
            float4 v0 = *reinterpret_cast<const float4*>(r16_h + (size_t)s0 * 128 + c0);
            float4 v1 = *reinterpret_cast<const float4*>(r16_h + (size_t)s1 * 128 + c0);
            float4 v2 = *reinterpret_cast<const float4*>(r16_h + (size_t)s2 * 128 + c0);
            float4 v3 = *reinterpret_cast<const float4*>(r16_h + (size_t)s3 * 128 + c0);
            acc.x += v0.x; acc.y += v0.y; acc.z += v0.z; acc.w += v0.w;
            acc.x += v1.x; acc.y += v1.y; acc.z += v1.z; acc.w += v1.w;
            acc.x += v2.x; acc.y += v2.y; acc.z += v2.z; acc.w += v2.w;
            acc.x += v3.x; acc.y += v3.y; acc.z += v3.z; acc.w += v3.w;
        }
        for (; jj < m; jj++) {
            int s = __shfl_sync(0xffffffffu, c, jj);
            float4 v = *reinterpret_cast<const float4*>(r16_h + (size_t)s * 128 + c0);
            acc.x += v.x; acc.y += v.y; acc.z += v.z; acc.w += v.w;
        }
    }
    float di = r16_dinv[i];
    float4 bb = *reinterpret_cast<const float4*>(b1 + c0);
    float4 r;
    r.x = fmaxf(acc.x * di + bb.x, 0.f); r.y = fmaxf(acc.y * di + bb.y, 0.f);
    r.z = fmaxf(acc.z * di + bb.z, 0.f); r.w = fmaxf(acc.w * di + bb.w, 0.f);
    *reinterpret_cast<float4*>(r16_a + (size_t)i * 128 + c0) = r;
}

__global__ void __launch_bounds__(256) r16_agg2(const float* __restrict__ b2,
                                                float* __restrict__ out, int n) {
    int warp = (blockIdx.x * blockDim.x + threadIdx.x) >> 5;
    int lane = threadIdx.x & 31;
    if (warp >= n) return;
    int i = warp, c0 = lane * 2;
    float2 acc = *reinterpret_cast<const float2*>(r16_h + (size_t)i * 64 + c0);
    int start = r16_rs[i], deg = r16_cnt[i];
    for (int j = 0; j < deg; j += 32) {
        int c = (j + lane < deg) ? r16_col[start + j + lane] : 0;
        int m = min(32, deg - j);
        int jj = 0;
        for (; jj + 4 <= m; jj += 4) {
            int s0 = __shfl_sync(0xffffffffu, c, jj);
            int s1 = __shfl_sync(0xffffffffu, c, jj + 1);
            int s2 = __shfl_sync(0xffffffffu, c, jj + 2);
            int s3 = __shfl_sync(0xffffffffu, c, jj + 3);
            float2 v0 = *reinterpret_cast<const float2*>(r16_h + (size_t)s0 * 64 + c0);
            float2 v1 = *reinterpret_cast<const float2*>(r16_h + (size_t)s1 * 64 + c0);
            float2 v2 = *reinterpret_cast<const float2*>(r16_h + (size_t)s2 * 64 + c0);
            float2 v3 = *reinterpret_cast<const float2*>(r16_h + (size_t)s3 * 64 + c0);
            acc.x += v0.x; acc.y += v0.y;
            acc.x += v1.x; acc.y += v1.y;
            acc.x += v2.x; acc.y += v2.y;
            acc.x += v3.x; acc.y += v3.y;
        }
        for (; jj < m; jj++) {
            int s = __shfl_sync(0xffffffffu, c, jj);
            float2 v = *reinterpret_cast<const float2*>(r16_h + (size_t)s * 64 + c0);
            acc.x += v.x; acc.y += v.y;
        }
    }
    float di = r16_dinv[i];
    float2 bb = *reinterpret_cast<const float2*>(b2 + c0);
    float vx = acc.x * di + bb.x, vy = acc.y * di + bb.y;
    float mx = fmaxf(vx, vy);
#pragma unroll
    for (int off = 16; off > 0; off >>= 1)
        mx = fmaxf(mx, __shfl_xor_sync(0xffffffffu, mx, off));
    float s = expf(vx - mx) + expf(vy - mx);
#pragma unroll
    for (int off = 16; off > 0; off >>= 1)
        s += __shfl_xor_sync(0xffffffffu, s, off);
    float lse = mx + logf(s);
    out[(size_t)i * 64 + c0]     = vx - lse;
    out[(size_t)i * 64 + c0 + 1] = vy - lse;
}

// ---------------- launch ------------------------------------------------------
extern "C" void kernel_launch(void* const* d_in, const int* in_sizes, int n_in,
                              void* d_out, int out_size) {
    const float *x = nullptr, *W1 = nullptr, *b1 = nullptr, *W2 = nullptr, *b2 = nullptr;
    const int* ep = nullptr; int S = 0;
    for (int i = 0; i < n_in; i++) {
        int s = in_sizes[i];
        if      (s == NN * DIN)    x  = (const float*)d_in[i];
        else if (s == DIN * DHID)  W1 = (const float*)d_in[i];
        else if (s == DHID * NCLS) W2 = (const float*)d_in[i];
        else if (s == DHID)        b1 = (const float*)d_in[i];
        else if (s == NCLS)        b2 = (const float*)d_in[i];
        else if (!ep)              { ep = (const int*)d_in[i]; S = s; }
    }
    float* out = (float*)d_out;
    if (!x || !W1 || !b1 || !W2 || !b2 || !ep || S < 2) return;

    int e = S / 2, n = NN;
    int nb = (n + 1023) / 1024;

    r16_zcnt<<<(n + 255) / 256, 256>>>(n);
    r16_hist<<<(e + 255) / 256, 256>>>(ep, e, n);
    r16_dinvk<<<(n + 255) / 256, 256>>>(n);
    r16_scan1<<<nb, 1024>>>(n);
    r16_scan2<<<1, 256>>>(nb);
    r16_scan3<<<nb, 1024>>>(n);
    r16_fill<<<(e + 255) / 256, 256>>>(ep, e, n);

    int gblocks = (n + 127) / 128;
    r16_gemm<128, 2, 0><<<gblocks, 256>>>(x, W1, n);        // h = dinv*(x@W1)
    r16_agg1<<<(n + 7) / 8, 256>>>(b1, n);                  // a = relu(dinv*agg+b1)
    r16_gemm<64, 1, 1><<<gblocks, 256>>>(nullptr, W2, n);   // h = dinv*(a@W2)
    r16_agg2<<<(n + 7) / 8, 256>>>(b2, out, n);             // out = log_softmax
}

// round 17
// speedup vs baseline: 1.4677x; 1.4677x over previous
#include <cuda_runtime.h>
#include <cuda_fp16.h>
#include <cstdint>

#define NN 100000
#define NE 1600000
#define DIN 128
#define DHID 128
#define NCLS 64

// ---------------- device scratch — symbols only, NEVER passed from host ------
__device__ __align__(16) __half r17_h[(size_t)NN * 128];   // fp16 gather source
__device__ __align__(16) float  r17_a[(size_t)NN * 128];
__device__ __align__(16) float  r17_dinv[NN];
__device__ __align__(16) int    r17_cnt[NN];
__device__ __align__(16) int    r17_rs[NN];
__device__ __align__(16) int    r17_wcur[NN];
__device__ __align__(16) int    r17_col[NE];
__device__ __align__(16) int    r17_bsum[256];

// ---------------- graph build (int32 planar [2,E]) ---------------------------
__global__ void r17_zcnt(int n) {
    int i = blockIdx.x * blockDim.x + threadIdx.x;
    if (i < n) r17_cnt[i] = 0;
}
__global__ void r17_hist(const int* __restrict__ ep, int e, int n) {
    int i = blockIdx.x * blockDim.x + threadIdx.x;
    if (i < e) {
        int d = ep[e + i];
        if (d >= 0 && d < n) atomicAdd(&r17_cnt[d], 1);
    }
}
__global__ void r17_dinvk(int n) {
    int i = blockIdx.x * blockDim.x + threadIdx.x;
    if (i < n) r17_dinv[i] = rsqrtf((float)(r17_cnt[i] + 1));   // +1 self loop
}
__global__ void r17_scan1(int n) {
    __shared__ int s[1024];
    int lid = threadIdx.x, gid = blockIdx.x * 1024 + lid;
    int v = (gid < n) ? r17_cnt[gid] : 0;
    s[lid] = v; __syncthreads();
    for (int off = 1; off < 1024; off <<= 1) {
        int t = (lid >= off) ? s[lid - off] : 0;
        __syncthreads(); s[lid] += t; __syncthreads();
    }
    if (gid < n) r17_rs[gid] = s[lid] - v;
    if (lid == 1023) r17_bsum[blockIdx.x] = s[1023];
}
__global__ void r17_scan2(int nb) {
    __shared__ int s[256];
    int lid = threadIdx.x;
    int v = (lid < nb) ? r17_bsum[lid] : 0;
    s[lid] = v; __syncthreads();
    for (int off = 1; off < 256; off <<= 1) {
        int t = (lid >= off) ? s[lid - off] : 0;
        __syncthreads(); s[lid] += t; __syncthreads();
    }
    if (lid < nb) r17_bsum[lid] = s[lid] - v;
}
__global__ void r17_scan3(int n) {
    int gid = blockIdx.x * 1024 + threadIdx.x;
    if (gid < n) {
        int r = r17_rs[gid] + r17_bsum[blockIdx.x];
        r17_rs[gid] = r; r17_wcur[gid] = r;
    }
}
__global__ void r17_fill(const int* __restrict__ ep, int e, int n) {
    int i = blockIdx.x * blockDim.x + threadIdx.x;
    if (i < e) {
        int s = ep[i], d = ep[e + i];
        if (d >= 0 && d < n && s >= 0 && s < n) {
            int pos = atomicAdd(&r17_wcur[d], 1);
            if (pos >= 0 && pos < NE) r17_col[pos] = s;
        }
    }
}

// ---------------- scalar-FFMA GEMM (proven R15), fp16 output -----------------
// r17_h[row,:] = half( dinv[row] * (X[row,:] @ W) ).  SRC=0: X=param; 1: X=r17_a
template <int BN, int NCH, int SRC>
__global__ void __launch_bounds__(256) r17_gemm(
    const float* __restrict__ Xparam, const float* __restrict__ W, int nrows)
{
    constexpr int BM = 128, BK = 16;
    __shared__ float Xs[BK][BM + 1];
    __shared__ float Ws[BK][BN];
    const float* X = (SRC == 0) ? Xparam : r17_a;

    int t = threadIdx.x, rg = t >> 4, cg = t & 15;
    int blockRow = blockIdx.x * BM;

    float acc[8][4 * NCH];
#pragma unroll
    for (int i = 0; i < 8; i++)
#pragma unroll
        for (int j = 0; j < 4 * NCH; j++) acc[i][j] = 0.f;

    for (int kb = 0; kb < 128; kb += BK) {
#pragma unroll
        for (int it = 0; it < 2; it++) {
            int f = t + it * 256, row = f >> 2, kq = (f & 3) * 4;
            float4 v = make_float4(0.f, 0.f, 0.f, 0.f);
            int gr = blockRow + row;
            if (gr < nrows)
                v = *reinterpret_cast<const float4*>(X + (size_t)gr * 128 + kb + kq);
            Xs[kq + 0][row] = v.x; Xs[kq + 1][row] = v.y;
            Xs[kq + 2][row] = v.z; Xs[kq + 3][row] = v.w;
        }
#pragma unroll
        for (int it = 0; it < (BK * BN) / 256; it++) {
            int f = t + it * 256;
            Ws[f / BN][f % BN] = W[(size_t)(kb + f / BN) * BN + f % BN];
        }
        __syncthreads();
#pragma unroll
        for (int k = 0; k < BK; k++) {
            float av[8];
#pragma unroll
            for (int i = 0; i < 4; i++) {
                av[i] = Xs[k][rg * 4 + i];
                av[i + 4] = Xs[k][64 + rg * 4 + i];
            }
            float bv[4 * NCH];
#pragma unroll
            for (int h = 0; h < NCH; h++)
#pragma unroll
                for (int j = 0; j < 4; j++)
                    bv[h * 4 + j] = Ws[k][h * 64 + cg * 4 + j];
#pragma unroll
            for (int i = 0; i < 8; i++)
#pragma unroll
                for (int j = 0; j < 4 * NCH; j++)
                    acc[i][j] += av[i] * bv[j];
        }
        __syncthreads();
    }
#pragma unroll
    for (int i = 0; i < 8; i++) {
        int row = blockRow + ((i < 4) ? (rg * 4 + i) : (64 + rg * 4 + i - 4));
        if (row < nrows) {
            float di = r17_dinv[row];
#pragma unroll
            for (int h = 0; h < NCH; h++) {
                __half2 h01 = __floats2half2_rn(acc[i][h * 4 + 0] * di,
                                                acc[i][h * 4 + 1] * di);
                __half2 h23 = __floats2half2_rn(acc[i][h * 4 + 2] * di,
                                                acc[i][h * 4 + 3] * di);
                uint2 u;
                u.x = *reinterpret_cast<unsigned int*>(&h01);
                u.y = *reinterpret_cast<unsigned int*>(&h23);
                *reinterpret_cast<uint2*>(r17_h + (size_t)row * BN + h * 64 + cg * 4) = u;
            }
        }
    }
}

// ---------------- layer-1 aggregation: fp16 gather, fp32 accumulate ----------
__device__ __forceinline__ void r17_add4(float4& acc, uint2 u) {
    __half2 h01 = *reinterpret_cast<__half2*>(&u.x);
    __half2 h23 = *reinterpret_cast<__half2*>(&u.y);
    float2 f01 = __half22float2(h01);
    float2 f23 = __half22float2(h23);
    acc.x += f01.x; acc.y += f01.y; acc.z += f23.x; acc.w += f23.y;
}

__global__ void __launch_bounds__(256) r17_agg1(const float* __restrict__ b1, int n) {
    int warp = (blockIdx.x * blockDim.x + threadIdx.x) >> 5;
    int lane = threadIdx.x & 31;
    if (warp >= n) return;
    int i = warp, c0 = lane * 4;
    float4 acc = make_float4(0.f, 0.f, 0.f, 0.f);
    r17_add4(acc, *reinterpret_cast<const uint2*>(r17_h + (size_t)i * 128 + c0));  // self
    int start = r17_rs[i], deg = r17_cnt[i];
    for (int j = 0; j < deg; j += 32) {
        int c = (j + lane < deg) ? r17_col[start + j + lane] : 0;
        int m = min(32, deg - j);
        int jj = 0;
        for (; jj + 4 <= m; jj += 4) {
            int s0 = __shfl_sync(0xffffffffu, c, jj);
            int s1 = __shfl_sync(0xffffffffu, c, jj + 1);
            int s2 = __shfl_sync(0xffffffffu, c, jj + 2);
            int s3 = __shfl_sync(0xffffffffu, c, jj + 3);
            uint2 u0 = *reinterpret_cast<const uint2*>(r17_h + (size_t)s0 * 128 + c0);
            uint2 u1 = *reinterpret_cast<const uint2*>(r17_h + (size_t)s1 * 128 + c0);
            uint2 u2 = *reinterpret_cast<const uint2*>(r17_h + (size_t)s2 * 128 + c0);
            uint2 u3 = *reinterpret_cast<const uint2*>(r17_h + (size_t)s3 * 128 + c0);
            r17_add4(acc, u0); r17_add4(acc, u1);
            r17_add4(acc, u2); r17_add4(acc, u3);
        }
        for (; jj < m; jj++) {
            int s = __shfl_sync(0xffffffffu, c, jj);
            r17_add4(acc, *reinterpret_cast<const uint2*>(r17_h + (size_t)s * 128 + c0));
        }
    }
    float di = r17_dinv[i];
    float4 bb = *reinterpret_cast<const float4*>(b1 + c0);
    float4 r;
    r.x = fmaxf(acc.x * di + bb.x, 0.f); r.y = fmaxf(acc.y * di + bb.y, 0.f);
    r.z = fmaxf(acc.z * di + bb.z, 0.f); r.w = fmaxf(acc.w * di + bb.w, 0.f);
    *reinterpret_cast<float4*>(r17_a + (size_t)i * 128 + c0) = r;
}

// ---------------- layer-2 aggregation + log_softmax --------------------------
__global__ void __launch_bounds__(256) r17_agg2(const float* __restrict__ b2,
                                                float* __restrict__ out, int n) {
    int warp = (blockIdx.x * blockDim.x + threadIdx.x) >> 5;
    int lane = threadIdx.x & 31;
    if (warp >= n) return;
    int i = warp, c0 = lane * 2;
    __half2 hv = *reinterpret_cast<const __half2*>(r17_h + (size_t)i * 64 + c0);
    float2 f = __half22float2(hv);
    float ax = f.x, ay = f.y;
    int start = r17_rs[i], deg = r17_cnt[i];
    for (int j = 0; j < deg; j += 32) {
        int c = (j + lane < deg) ? r17_col[start + j + lane] : 0;
        int m = min(32, deg - j);
        int jj = 0;
        for (; jj + 4 <= m; jj += 4) {
            int s0 = __shfl_sync(0xffffffffu, c, jj);
            int s1 = __shfl_sync(0xffffffffu, c, jj + 1);
            int s2 = __shfl_sync(0xffffffffu, c, jj + 2);
            int s3 = __shfl_sync(0xffffffffu, c, jj + 3);
            __half2 v0 = *reinterpret_cast<const __half2*>(r17_h + (size_t)s0 * 64 + c0);
            __half2 v1 = *reinterpret_cast<const __half2*>(r17_h + (size_t)s1 * 64 + c0);
            __half2 v2 = *reinterpret_cast<const __half2*>(r17_h + (size_t)s2 * 64 + c0);
            __half2 v3 = *reinterpret_cast<const __half2*>(r17_h + (size_t)s3 * 64 + c0);
            float2 g0 = __half22float2(v0), g1 = __half22float2(v1);
            float2 g2 = __half22float2(v2), g3 = __half22float2(v3);
            ax += g0.x + g1.x + g2.x + g3.x;
            ay += g0.y + g1.y + g2.y + g3.y;
        }
        for (; jj < m; jj++) {
            int s = __shfl_sync(0xffffffffu, c, jj);
            float2 g = __half22float2(
                *reinterpret_cast<const __half2*>(r17_h + (size_t)s * 64 + c0));
            ax += g.x; ay += g.y;
        }
    }
    float di = r17_dinv[i];
    float vx = ax * di + b2[c0];
    float vy = ay * di + b2[c0 + 1];
    float mx = fmaxf(vx, vy);
#pragma unroll
    for (int off = 16; off > 0; off >>= 1)
        mx = fmaxf(mx, __shfl_xor_sync(0xffffffffu, mx, off));
    float s = expf(vx - mx) + expf(vy - mx);
#pragma unroll
    for (int off = 16; off > 0; off >>= 1)
        s += __shfl_xor_sync(0xffffffffu, s, off);
    float lse = mx + logf(s);
    out[(size_t)i * 64 + c0]     = vx - lse;
    out[(size_t)i * 64 + c0 + 1] = vy - lse;
}

// ---------------- launch ------------------------------------------------------
extern "C" void kernel_launch(void* const* d_in, const int* in_sizes, int n_in,
                              void* d_out, int out_size) {
    const float *x = nullptr, *W1 = nullptr, *b1 = nullptr, *W2 = nullptr, *b2 = nullptr;
    const int* ep = nullptr; int S = 0;
    for (int i = 0; i < n_in; i++) {
        int s = in_sizes[i];
        if      (s == NN * DIN)    x  = (const float*)d_in[i];
        else if (s == DIN * DHID)  W1 = (const float*)d_in[i];
        else if (s == DHID * NCLS) W2 = (const float*)d_in[i];
        else if (s == DHID)        b1 = (const float*)d_in[i];
        else if (s == NCLS)        b2 = (const float*)d_in[i];
        else if (!ep)              { ep = (const int*)d_in[i]; S = s; }
    }
    float* out = (float*)d_out;
    if (!x || !W1 || !b1 || !W2 || !b2 || !ep || S < 2) return;

    int e = S / 2, n = NN;
    int nb = (n + 1023) / 1024;

    r17_zcnt<<<(n + 255) / 256, 256>>>(n);
    r17_hist<<<(e + 255) / 256, 256>>>(ep, e, n);
    r17_dinvk<<<(n + 255) / 256, 256>>>(n);
    r17_scan1<<<nb, 1024>>>(n);
    r17_scan2<<<1, 256>>>(nb);
    r17_scan3<<<nb, 1024>>>(n);
    r17_fill<<<(e + 255) / 256, 256>>>(ep, e, n);

    int gblocks = (n + 127) / 128;
    r17_gemm<128, 2, 0><<<gblocks, 256>>>(x, W1, n);        // h = fp16(dinv*(x@W1))
    r17_agg1<<<(n + 7) / 8, 256>>>(b1, n);                  // a = relu(dinv*agg+b1)
    r17_gemm<64, 1, 1><<<gblocks, 256>>>(nullptr, W2, n);   // h = fp16(dinv*(a@W2))
    r17_agg2<<<(n + 7) / 8, 256>>>(b2, out, n);             // out = log_softmax
}